// round 4
// baseline (speedup 1.0000x reference)
#include <cuda_runtime.h>
#include <cstdint>

#define BB 64
#define NN 8192
#define WW 64
#define HH 4
#define EPSF 1e-8f
#define NCHUNK 32          // 8192 / 256 rows per block

// ---------------- scratch (device globals; no allocation allowed) ----------------
__device__ float g_e[BB * NN * HH];              // exp(beta*(cos-1)), layout [b][n][h]
__device__ float g_ws[BB * NN * HH];             // unnormalized sharpened weights, [b][n][h]
__device__ float g_parte[BB * HH * NCHUNK];      // partial sums of e   [(b*4+h)*32 + chunk]
__device__ float g_partw[BB * HH * NCHUNK];      // partial sums of ws  [(b*4+h)*32 + chunk]
__device__ float g_parto[NCHUNK * BB * HH * WW]; // partial outputs [chunk][b][h][w]

__device__ __forceinline__ float softplusf(float x) {
    return (x > 20.f) ? x : log1pf(expf(x));
}

// =====================================================================
// Kernel A: content addressing -> e = exp(beta*(cos - 1))
// grid (32, 64), block 256. Thread = one memory row; all 4 heads per thread.
// Row streamed directly from global (no smem staging); keys via LDS broadcast.
// =====================================================================
__global__ void __launch_bounds__(256) k_scores(const float* __restrict__ mem,
                                                const float* __restrict__ ctrl) {
    __shared__ float4 s_keys[4][16];    // [h][j] float4 = keys[h][64]
    __shared__ float  s_nk[4], s_beta[4];
    __shared__ float4 s_wred[8];

    const int b   = blockIdx.y;
    const int tid = threadIdx.x;
    const float* cb = ctrl + b * 280;

    {
        int kh = tid >> 6, kw = tid & 63;
        ((float*)s_keys)[kh * 64 + kw] = tanhf(cb[kh * 64 + kw]);
    }
    if (tid < 4) s_beta[tid] = softplusf(cb[256 + tid]);
    __syncthreads();
    if (tid < 4) {
        const float* kk = (const float*)s_keys + tid * 64;
        float s = 0.f;
        #pragma unroll
        for (int w = 0; w < 64; w++) s = fmaf(kk[w], kk[w], s);
        s_nk[tid] = sqrtf(s);
    }
    __syncthreads();

    const int n = blockIdx.x * 256 + tid;
    const float4* row = (const float4*)(mem + ((size_t)b * NN + n) * WW);

    float d0 = 0.f, d1 = 0.f, d2 = 0.f, d3 = 0.f, nm2 = 0.f;
    #pragma unroll 4
    for (int j = 0; j < 16; j++) {
        float4 m = row[j];
        nm2 = fmaf(m.x, m.x, nm2); nm2 = fmaf(m.y, m.y, nm2);
        nm2 = fmaf(m.z, m.z, nm2); nm2 = fmaf(m.w, m.w, nm2);
        float4 k0 = s_keys[0][j];
        d0 = fmaf(m.x, k0.x, d0); d0 = fmaf(m.y, k0.y, d0);
        d0 = fmaf(m.z, k0.z, d0); d0 = fmaf(m.w, k0.w, d0);
        float4 k1 = s_keys[1][j];
        d1 = fmaf(m.x, k1.x, d1); d1 = fmaf(m.y, k1.y, d1);
        d1 = fmaf(m.z, k1.z, d1); d1 = fmaf(m.w, k1.w, d1);
        float4 k2 = s_keys[2][j];
        d2 = fmaf(m.x, k2.x, d2); d2 = fmaf(m.y, k2.y, d2);
        d2 = fmaf(m.z, k2.z, d2); d2 = fmaf(m.w, k2.w, d2);
        float4 k3 = s_keys[3][j];
        d3 = fmaf(m.x, k3.x, d3); d3 = fmaf(m.y, k3.y, d3);
        d3 = fmaf(m.z, k3.z, d3); d3 = fmaf(m.w, k3.w, d3);
    }
    const float nmr = sqrtf(nm2);
    float4 e;
    e.x = expf(s_beta[0] * (d0 / (nmr * s_nk[0] + EPSF) - 1.f));
    e.y = expf(s_beta[1] * (d1 / (nmr * s_nk[1] + EPSF) - 1.f));
    e.z = expf(s_beta[2] * (d2 / (nmr * s_nk[2] + EPSF) - 1.f));
    e.w = expf(s_beta[3] * (d3 / (nmr * s_nk[3] + EPSF) - 1.f));
    *(float4*)(g_e + ((size_t)b * NN + n) * 4) = e;

    // block reduction of e per head: warp shfl, then 8 warp-partials
    float4 v = e;
    #pragma unroll
    for (int off = 16; off > 0; off >>= 1) {
        v.x += __shfl_down_sync(0xffffffffu, v.x, off);
        v.y += __shfl_down_sync(0xffffffffu, v.y, off);
        v.z += __shfl_down_sync(0xffffffffu, v.z, off);
        v.w += __shfl_down_sync(0xffffffffu, v.w, off);
    }
    if ((tid & 31) == 0) s_wred[tid >> 5] = v;
    __syncthreads();
    if (tid == 0) {
        float4 t = s_wred[0];
        #pragma unroll
        for (int i = 1; i < 8; i++) {
            float4 a = s_wred[i];
            t.x += a.x; t.y += a.y; t.z += a.z; t.w += a.w;
        }
        float* p = g_parte + b * 4 * NCHUNK + blockIdx.x;
        p[0] = t.x; p[NCHUNK] = t.y; p[2 * NCHUNK] = t.z; p[3 * NCHUNK] = t.w;
    }
}

// =====================================================================
// Kernel B: softmax-normalize, interpolate, circular shift, sharpen
// grid (32, 64), block 256 -> one thread per n, all 4 heads.
// =====================================================================
__global__ void __launch_bounds__(256) k_weights(const float* __restrict__ ctrl,
                                                 const float* __restrict__ prev) {
    __shared__ float s_g[4], s_sh0[4], s_sh1[4], s_sh2[4], s_gam[4], s_inv[4];
    __shared__ float4 s_red[256];

    const int b = blockIdx.y;
    const int tid = threadIdx.x;

    if (tid < 4) {
        const float* cb = ctrl + b * 280;
        s_g[tid]   = 1.f / (1.f + expf(-cb[260 + tid]));
        s_gam[tid] = 1.f + softplusf(cb[276 + tid]);
        float a0 = cb[264 + tid * 3], a1 = cb[265 + tid * 3], a2 = cb[266 + tid * 3];
        float mx = fmaxf(a0, fmaxf(a1, a2));
        float e0 = expf(a0 - mx), e1 = expf(a1 - mx), e2 = expf(a2 - mx);
        float inv3 = 1.f / (e0 + e1 + e2);
        s_sh0[tid] = e0 * inv3; s_sh1[tid] = e1 * inv3; s_sh2[tid] = e2 * inv3;
        const float* pe = g_parte + (b * 4 + tid) * NCHUNK;
        float s = 0.f;
        #pragma unroll
        for (int c = 0; c < NCHUNK; c++) s += pe[c];
        s_inv[tid] = 1.f / s;          // softmax denominator (no EPS per reference)
    }
    __syncthreads();

    const int n  = blockIdx.x * 256 + tid;
    const int nm = (n - 1) & (NN - 1);
    const int np = (n + 1) & (NN - 1);

    const float4* eb = (const float4*)(g_e + (size_t)b * NN * 4);
    float4 em4 = eb[nm], ec4 = eb[n], ep4 = eb[np];
    float emv[4] = {em4.x, em4.y, em4.z, em4.w};
    float ecv[4] = {ec4.x, ec4.y, ec4.z, ec4.w};
    float epv[4] = {ep4.x, ep4.y, ep4.z, ep4.w};

    const float* pb = prev + (size_t)b * HH * NN;

    float wo[4];
    #pragma unroll
    for (int h = 0; h < 4; h++) {
        float g = s_g[h], inv = s_inv[h], om = 1.f - g;
        float wim = fmaf(g, emv[h] * inv, om * pb[h * NN + nm]);
        float wic = fmaf(g, ecv[h] * inv, om * pb[h * NN + n]);
        float wip = fmaf(g, epv[h] * inv, om * pb[h * NN + np]);
        float wsf = s_sh0[h] * wim + s_sh1[h] * wic + s_sh2[h] * wip;
        wo[h] = __powf(wsf, s_gam[h]);   // wsf > 0 always
    }
    *(float4*)(g_ws + ((size_t)b * NN + n) * 4) = make_float4(wo[0], wo[1], wo[2], wo[3]);

    s_red[tid] = make_float4(wo[0], wo[1], wo[2], wo[3]);
    __syncthreads();
    #pragma unroll
    for (int s = 128; s > 0; s >>= 1) {
        if (tid < s) {
            float4 a = s_red[tid], c = s_red[tid + s];
            s_red[tid] = make_float4(a.x + c.x, a.y + c.y, a.z + c.z, a.w + c.w);
        }
        __syncthreads();
    }
    if (tid < 4) {
        float4 tot = s_red[0];
        float v = (tid == 0) ? tot.x : (tid == 1) ? tot.y : (tid == 2) ? tot.z : tot.w;
        g_partw[(b * 4 + tid) * NCHUNK + blockIdx.x] = v;
    }
}

// =====================================================================
// Kernel C: read = sum_n mem[b][n][w] * ws_norm[b][h][n]  (partial per chunk)
// grid (32, 64), block 256. Thread = (rsub, w4); each smem float4 read ONCE,
// all 4 heads accumulated by the same thread (4 float4 accumulators).
// =====================================================================
__global__ void __launch_bounds__(256) k_read(const float* __restrict__ mem) {
    __shared__ float s_mem[64][68];     // 17408 B; reused as s_red[16][64] float4 at end
    __shared__ float s_wall[4][256];    // chunk weights [h][row]
    __shared__ float s_inv[4];

    const int b = blockIdx.y;
    const int tid = threadIdx.x;
    const int n0 = blockIdx.x * 256;

    if (tid < 4) {
        const float* pw = g_partw + (b * 4 + tid) * NCHUNK;
        float s = 0.f;
        #pragma unroll
        for (int c = 0; c < NCHUNK; c++) s += pw[c];
        s_inv[tid] = 1.f / (s + EPSF);
    }
    {
        float4 wv = *(const float4*)(g_ws + ((size_t)b * NN + n0 + tid) * 4);
        s_wall[0][tid] = wv.x; s_wall[1][tid] = wv.y;
        s_wall[2][tid] = wv.z; s_wall[3][tid] = wv.w;
    }

    const int rsub = tid >> 4;      // 0..15
    const int w4   = tid & 15;      // 0..15
    const float* memb = mem + (size_t)b * NN * WW;

    float4 a0 = make_float4(0.f,0.f,0.f,0.f);
    float4 a1 = a0, a2 = a0, a3 = a0;

    for (int t = 0; t < 4; t++) {
        __syncthreads();
        const float4* src = (const float4*)(memb + (size_t)(n0 + t * 64) * WW);
        #pragma unroll
        for (int i = 0; i < 4; i++) {
            int idx = tid + i * 256;
            *(float4*)&s_mem[idx >> 4][(idx & 15) * 4] = src[idx];
        }
        __syncthreads();
        #pragma unroll
        for (int rr = 0; rr < 4; rr++) {
            int r = rr * 16 + rsub;
            float4 m = *(const float4*)&s_mem[r][w4 * 4];
            int gr = t * 64 + r;
            float w0 = s_wall[0][gr], w1 = s_wall[1][gr];
            float w2 = s_wall[2][gr], w3 = s_wall[3][gr];
            a0.x = fmaf(w0, m.x, a0.x); a0.y = fmaf(w0, m.y, a0.y);
            a0.z = fmaf(w0, m.z, a0.z); a0.w = fmaf(w0, m.w, a0.w);
            a1.x = fmaf(w1, m.x, a1.x); a1.y = fmaf(w1, m.y, a1.y);
            a1.z = fmaf(w1, m.z, a1.z); a1.w = fmaf(w1, m.w, a1.w);
            a2.x = fmaf(w2, m.x, a2.x); a2.y = fmaf(w2, m.y, a2.y);
            a2.z = fmaf(w2, m.z, a2.z); a2.w = fmaf(w2, m.w, a2.w);
            a3.x = fmaf(w3, m.x, a3.x); a3.y = fmaf(w3, m.y, a3.y);
            a3.z = fmaf(w3, m.z, a3.z); a3.w = fmaf(w3, m.w, a3.w);
        }
    }

    __syncthreads();                       // all s_mem readers done; reuse as s_red
    float4* s_red = (float4*)s_mem;        // [rsub][h*16+w4] -> 16 x 64 float4
    s_red[rsub * 64 +  0 + w4] = a0;
    s_red[rsub * 64 + 16 + w4] = a1;
    s_red[rsub * 64 + 32 + w4] = a2;
    s_red[rsub * 64 + 48 + w4] = a3;
    __syncthreads();
    if (tid < 64) {
        float4 acc = s_red[tid];
        #pragma unroll
        for (int k = 1; k < 16; k++) {
            float4 a = s_red[k * 64 + tid];
            acc.x += a.x; acc.y += a.y; acc.z += a.z; acc.w += a.w;
        }
        float inv = s_inv[tid >> 4];
        acc.x *= inv; acc.y *= inv; acc.z *= inv; acc.w *= inv;
        // tid = h*16+w4 -> output offset h*64 + w4*4 = tid*4
        *(float4*)(g_parto + (size_t)blockIdx.x * (BB * HH * WW) + b * 256 + tid * 4) = acc;
    }
}

// =====================================================================
// Kernel D: sum 32 chunk partials -> out [B,H,W]
// grid 256 x 64 threads: all SMs engaged, coalesced per-chunk loads.
// =====================================================================
__global__ void __launch_bounds__(64) k_final(float* __restrict__ out) {
    const int i = blockIdx.x * 64 + threadIdx.x;   // 0..16383
    float s = 0.f;
    #pragma unroll
    for (int c = 0; c < NCHUNK; c++)
        s += g_parto[(size_t)c * (BB * HH * WW) + i];
    out[i] = s;
}

// =====================================================================
extern "C" void kernel_launch(void* const* d_in, const int* in_sizes, int n_in,
                              void* d_out, int out_size) {
    const float* mem  = nullptr;
    const float* ctrl = nullptr;
    const float* prev = nullptr;
    for (int i = 0; i < n_in; i++) {
        if (in_sizes[i] == BB * NN * WW)      mem  = (const float*)d_in[i];
        else if (in_sizes[i] == BB * 280)     ctrl = (const float*)d_in[i];
        else if (in_sizes[i] == BB * HH * NN) prev = (const float*)d_in[i];
    }

    dim3 grid(NCHUNK, BB);
    k_scores <<<grid, 256>>>(mem, ctrl);
    k_weights<<<grid, 256>>>(ctrl, prev);
    k_read   <<<grid, 256>>>(mem);
    k_final  <<<256,  64>>>((float*)d_out);
}